// round 7
// baseline (speedup 1.0000x reference)
#include <cuda_runtime.h>
#include <cuda_bf16.h>
#include <cstdint>

#define NN 50000
#define EE 600000
#define D 128
#define HH 8

// ---------------- scratch (device globals; no dynamic allocation) ----------------
__device__ float g_h   [(size_t)NN * D];      // LN1 output
__device__ float g_q   [(size_t)NN * D];
__device__ float g_k   [(size_t)NN * D];
__device__ float g_v   [(size_t)NN * D];
__device__ float g_skip[(size_t)NN * D];
__device__ float g_z   [(size_t)NN * HH];     // segment sum of exp(logit)
__device__ float g_acc [(size_t)NN * D];      // segment sum of p*v (unnormalized)
__device__ float g_x2  [(size_t)NN * D];      // x + alpha*out
__device__ float g_h2  [(size_t)NN * D];      // LN2 output
__device__ float g_u   [(size_t)NN * 4 * D];  // FFN hidden

__device__ __forceinline__ int clampi(int v, int lo, int hi) {
    return v < lo ? lo : (v > hi ? hi : v);
}
__device__ __forceinline__ void red_v4(float* ptr, float a, float b, float c, float d) {
    asm volatile("red.global.v4.f32.add [%0], {%1,%2,%3,%4};"
                 :: "l"(ptr), "f"(a), "f"(b), "f"(c), "f"(d) : "memory");
}
__device__ __forceinline__ void red_f32(float* ptr, float a) {
    asm volatile("red.global.add.f32 [%0], %1;" :: "l"(ptr), "f"(a) : "memory");
}

// ---------------- arch-agnostic tensor-core helpers (sm_80+ PTX) ----------------
__device__ __forceinline__ uint32_t smem_u32(const void* p) {
    uint32_t a;
    asm("{ .reg .u64 t; cvta.to.shared.u64 t, %1; cvt.u32.u64 %0, t; }" : "=r"(a) : "l"(p));
    return a;
}
__device__ __forceinline__ void ldm_x4(uint32_t (&r)[4], uint32_t addr) {
    asm volatile("ldmatrix.sync.aligned.m8n8.x4.shared.b16 {%0,%1,%2,%3}, [%4];"
                 : "=r"(r[0]), "=r"(r[1]), "=r"(r[2]), "=r"(r[3]) : "r"(addr));
}
__device__ __forceinline__ void ldm_x2(uint32_t (&r)[2], uint32_t addr) {
    asm volatile("ldmatrix.sync.aligned.m8n8.x2.shared.b16 {%0,%1}, [%2];"
                 : "=r"(r[0]), "=r"(r[1]) : "r"(addr));
}
__device__ __forceinline__ void mma_bf16(float (&d)[4], const uint32_t (&a)[4],
                                         const uint32_t (&b)[2]) {
    asm volatile("mma.sync.aligned.m16n8k16.row.col.f32.bf16.bf16.f32 "
                 "{%0,%1,%2,%3}, {%4,%5,%6,%7}, {%8,%9}, {%0,%1,%2,%3};"
                 : "+f"(d[0]), "+f"(d[1]), "+f"(d[2]), "+f"(d[3])
                 : "r"(a[0]), "r"(a[1]), "r"(a[2]), "r"(a[3]), "r"(b[0]), "r"(b[1]));
}

// bf16 tile row stride (elements): 128 + 8 pad -> conflict-free ldmatrix
#define AST 136
// fp32 C tile row stride
#define CST 132

// dynamic smem byte offsets for k_edge_mma
#define SM_AH 0
#define SM_AL (SM_AH + 128 * AST * 2)   // 34816
#define SM_BH (SM_AL + 128 * AST * 2)   // 69632
#define SM_BL (SM_BH + 128 * AST * 2)   // 104448
#define EDGE_SMEM_BYTES (SM_BL + 128 * AST * 2)  // 139264
// C (fp32, 128 x CST = 67584 B) overlays SM_AH/SM_AL after the MMA phase

// ---------------- tensor-core fused edge pass ----------------
// Per block: 128 edges. C[128,128] = EA_tile @ We via bf16 hi/lo 3-term mma.sync.
// Then per-edge epilogue: gather k/v/q, p = exp(q.(k+e)/4), RED acc/z.
__global__ void __launch_bounds__(256) k_edge_mma(
        const float* __restrict__ ea_g, const int* __restrict__ ei,
        const float* __restrict__ We, int E, int n) {
    extern __shared__ char smem[];
    __nv_bfloat16* Ah = (__nv_bfloat16*)(smem + SM_AH);
    __nv_bfloat16* Al = (__nv_bfloat16*)(smem + SM_AL);
    __nv_bfloat16* Bh = (__nv_bfloat16*)(smem + SM_BH);
    __nv_bfloat16* Bl = (__nv_bfloat16*)(smem + SM_BL);
    int tx = threadIdx.x;
    int w = tx >> 5, lane = tx & 31;
    int e0 = blockIdx.x * 128;

    // --- convert EA tile [128 rows][128 cols] fp32 -> bf16 hi/lo ---
    for (int idx = tx; idx < 128 * 32; idx += 256) {
        int r = idx >> 5, c4 = idx & 31;
        int c = c4 * 4;
        float4 v = (e0 + r < E) ? ((const float4*)ea_g)[(size_t)(e0 + r) * 32 + c4]
                                : make_float4(0.f, 0.f, 0.f, 0.f);
        __nv_bfloat16 h0 = __float2bfloat16(v.x), h1 = __float2bfloat16(v.y);
        __nv_bfloat16 h2 = __float2bfloat16(v.z), h3 = __float2bfloat16(v.w);
        __nv_bfloat16 l0 = __float2bfloat16(v.x - __bfloat162float(h0));
        __nv_bfloat16 l1 = __float2bfloat16(v.y - __bfloat162float(h1));
        __nv_bfloat16 l2 = __float2bfloat16(v.z - __bfloat162float(h2));
        __nv_bfloat16 l3 = __float2bfloat16(v.w - __bfloat162float(h3));
        __nv_bfloat162* ph = (__nv_bfloat162*)&Ah[r * AST + c];
        ph[0] = __nv_bfloat162(h0, h1); ph[1] = __nv_bfloat162(h2, h3);
        __nv_bfloat162* pl = (__nv_bfloat162*)&Al[r * AST + c];
        pl[0] = __nv_bfloat162(l0, l1); pl[1] = __nv_bfloat162(l2, l3);
    }
    // --- convert We^T -> B[n][k] bf16 hi/lo ---
    for (int idx = tx; idx < 128 * 32; idx += 256) {
        int k = idx >> 5, n4 = idx & 31;
        int nb = n4 * 4;
        float4 v = ((const float4*)We)[(size_t)k * 32 + n4];
        float vals[4] = {v.x, v.y, v.z, v.w};
#pragma unroll
        for (int j = 0; j < 4; ++j) {
            __nv_bfloat16 h = __float2bfloat16(vals[j]);
            __nv_bfloat16 l = __float2bfloat16(vals[j] - __bfloat162float(h));
            Bh[(nb + j) * AST + k] = h;
            Bl[(nb + j) * AST + k] = l;
        }
    }
    __syncthreads();

    // --- MMA phase: warp w computes rows 16w..16w+15, all 128 cols ---
    float acc[16][4];
#pragma unroll
    for (int nt = 0; nt < 16; ++nt) {
        acc[nt][0] = 0.f; acc[nt][1] = 0.f; acc[nt][2] = 0.f; acc[nt][3] = 0.f;
    }
    {
        int R0 = w * 16;
        int arow = R0 + (lane & 15);
        int acolsel = (lane >> 4) << 3;          // 0 or 8
        int brow_in = lane & 7;
        int bcolsel = (lane & 8) ? 8 : 0;
        for (int kt = 0; kt < 8; ++kt) {
            int k0 = kt * 16;
            uint32_t ah[4], al[4];
            ldm_x4(ah, smem_u32(&Ah[arow * AST + k0 + acolsel]));
            ldm_x4(al, smem_u32(&Al[arow * AST + k0 + acolsel]));
#pragma unroll
            for (int nt = 0; nt < 16; ++nt) {
                int brow = nt * 8 + brow_in;
                uint32_t bh[2], bl[2];
                ldm_x2(bh, smem_u32(&Bh[brow * AST + k0 + bcolsel]));
                ldm_x2(bl, smem_u32(&Bl[brow * AST + k0 + bcolsel]));
                mma_bf16(acc[nt], ah, bh);
                mma_bf16(acc[nt], ah, bl);
                mma_bf16(acc[nt], al, bh);
            }
        }
    }
    __syncthreads();   // done reading Ah/Al; C overlays them

    // --- spill C fragments to smem ---
    float* C = (float*)smem;
    {
        int r0 = w * 16 + (lane >> 2);
        int cb = (lane & 3) * 2;
#pragma unroll
        for (int nt = 0; nt < 16; ++nt) {
            int c = nt * 8 + cb;
            C[r0 * CST + c]       = acc[nt][0];
            C[r0 * CST + c + 1]   = acc[nt][1];
            C[(r0 + 8) * CST + c]     = acc[nt][2];
            C[(r0 + 8) * CST + c + 1] = acc[nt][3];
        }
    }
    __syncthreads();

    // --- epilogue: thread handles row = tx&127, cols half*64..+63 ---
    {
        int row = tx & 127, half = tx >> 7;
        int e = e0 + row;
        if (e < E) {
            int src = clampi(ei[e], 0, n - 1);
            int dst = clampi(ei[(size_t)E + e], 0, n - 1);
            const float4* kp = (const float4*)&g_k[(size_t)src * D];
            const float4* vp = (const float4*)&g_v[(size_t)src * D];
            const float4* qp = (const float4*)&g_q[(size_t)dst * D];
            const float* crow = &C[row * CST];
#pragma unroll
            for (int hh = 0; hh < 4; ++hh) {
                int c16 = half * 64 + hh * 16;
                float logit = 0.f;
                float pv[16];
#pragma unroll
                for (int j = 0; j < 4; ++j) {
                    float4 ee = *(const float4*)&crow[c16 + j * 4];
                    float4 kq = kp[(c16 >> 2) + j];
                    float4 qq = qp[(c16 >> 2) + j];
                    float4 vv = vp[(c16 >> 2) + j];
                    logit = fmaf(qq.x, kq.x + ee.x, logit);
                    logit = fmaf(qq.y, kq.y + ee.y, logit);
                    logit = fmaf(qq.z, kq.z + ee.z, logit);
                    logit = fmaf(qq.w, kq.w + ee.w, logit);
                    pv[j * 4 + 0] = vv.x + ee.x;
                    pv[j * 4 + 1] = vv.y + ee.y;
                    pv[j * 4 + 2] = vv.z + ee.z;
                    pv[j * 4 + 3] = vv.w + ee.w;
                }
                float p = __expf(logit * 0.25f);  // 1/sqrt(16); shift-invariant softmax
#pragma unroll
                for (int j = 0; j < 4; ++j)
                    red_v4(&g_acc[(size_t)dst * D + c16 + j * 4],
                           p * pv[j * 4 + 0], p * pv[j * 4 + 1],
                           p * pv[j * 4 + 2], p * pv[j * 4 + 3]);
                red_f32(&g_z[(size_t)dst * HH + half * 4 + hh], p);
            }
        }
    }
}

// ---------------- shared SIMT GEMM inner body (R5) ----------------
__device__ __forceinline__ void gemm_chunk(const float (*AS)[128], const float (*WS)[128],
                                           int r0, int c0, int koff, float (&acc)[8][4]) {
#pragma unroll 2
    for (int k4 = 0; k4 < 8; ++k4) {
        float4 w0 = *(const float4*)&WS[k4 * 4 + 0][c0];
        float4 w1 = *(const float4*)&WS[k4 * 4 + 1][c0];
        float4 w2 = *(const float4*)&WS[k4 * 4 + 2][c0];
        float4 w3 = *(const float4*)&WS[k4 * 4 + 3][c0];
#pragma unroll
        for (int r = 0; r < 8; ++r) {
            float4 a = *(const float4*)&AS[r0 + r][koff + k4 * 4];
            acc[r][0] = fmaf(a.x, w0.x, acc[r][0]);
            acc[r][1] = fmaf(a.x, w0.y, acc[r][1]);
            acc[r][2] = fmaf(a.x, w0.z, acc[r][2]);
            acc[r][3] = fmaf(a.x, w0.w, acc[r][3]);
            acc[r][0] = fmaf(a.y, w1.x, acc[r][0]);
            acc[r][1] = fmaf(a.y, w1.y, acc[r][1]);
            acc[r][2] = fmaf(a.y, w1.z, acc[r][2]);
            acc[r][3] = fmaf(a.y, w1.w, acc[r][3]);
            acc[r][0] = fmaf(a.z, w2.x, acc[r][0]);
            acc[r][1] = fmaf(a.z, w2.y, acc[r][1]);
            acc[r][2] = fmaf(a.z, w2.z, acc[r][2]);
            acc[r][3] = fmaf(a.z, w2.w, acc[r][3]);
            acc[r][0] = fmaf(a.w, w3.x, acc[r][0]);
            acc[r][1] = fmaf(a.w, w3.y, acc[r][1]);
            acc[r][2] = fmaf(a.w, w3.z, acc[r][2]);
            acc[r][3] = fmaf(a.w, w3.w, acc[r][3]);
        }
    }
}

// ---------------- K1: LayerNorm1 (x -> g_h) ----------------
__global__ void k_ln1(const float* __restrict__ x, const float* __restrict__ g,
                      const float* __restrict__ b, int n) {
    int row = blockIdx.x * 8 + (threadIdx.x >> 5);
    if (row >= n) return;
    int lane = threadIdx.x & 31;
    float4 v = ((const float4*)x)[(size_t)row * 32 + lane];
    float s  = v.x + v.y + v.z + v.w;
    float ss = fmaf(v.x, v.x, fmaf(v.y, v.y, fmaf(v.z, v.z, v.w * v.w)));
#pragma unroll
    for (int o = 16; o > 0; o >>= 1) {
        s  += __shfl_xor_sync(0xFFFFFFFFu, s, o);
        ss += __shfl_xor_sync(0xFFFFFFFFu, ss, o);
    }
    float mu  = s * (1.0f / 128.0f);
    float var = ss * (1.0f / 128.0f) - mu * mu;
    float r   = rsqrtf(var + 1e-5f);
    float4 gg = ((const float4*)g)[lane];
    float4 bb = ((const float4*)b)[lane];
    float4 o4;
    o4.x = (v.x - mu) * r * gg.x + bb.x;
    o4.y = (v.y - mu) * r * gg.y + bb.y;
    o4.z = (v.z - mu) * r * gg.z + bb.z;
    o4.w = (v.w - mu) * r * gg.w + bb.w;
    ((float4*)g_h)[(size_t)row * 32 + lane] = o4;
}

// ---------------- K2: init segment buffers ----------------
__global__ void k_init(int n) {
    int i = blockIdx.x * blockDim.x + threadIdx.x;
    if (i < n * HH) g_z[i] = 0.0f;
    if (i < n * D)  g_acc[i] = 0.0f;
}

// ---------------- K3: fused node GEMMs (q,k,v,skip) ----------------
__global__ void __launch_bounds__(256) k_node_gemm(
        const float* __restrict__ Wq, const float* __restrict__ bq,
        const float* __restrict__ Wk, const float* __restrict__ bk,
        const float* __restrict__ Wv, const float* __restrict__ bv,
        const float* __restrict__ Ws, const float* __restrict__ bs, int n) {
    const float* W; const float* bias; float* out;
    switch (blockIdx.y) {
        case 0:  W = Wq; bias = bq; out = g_q;    break;
        case 1:  W = Wk; bias = bk; out = g_k;    break;
        case 2:  W = Wv; bias = bv; out = g_v;    break;
        default: W = Ws; bias = bs; out = g_skip; break;
    }
    __shared__ float as_[64][128];
    __shared__ float ws_[32][128];
    int tx = threadIdx.x;
    int row0 = blockIdx.x * 64;
    for (int i = tx; i < 64 * 32; i += 256) {
        int r = i >> 5, c4 = i & 31;
        float4 val = (row0 + r < n) ? ((const float4*)g_h)[(size_t)(row0 + r) * 32 + c4]
                                    : make_float4(0.f, 0.f, 0.f, 0.f);
        *(float4*)&as_[r][c4 * 4] = val;
    }
    int cg = tx & 31, rg = tx >> 5;
    int c0 = cg * 4, r0 = rg * 8;
    float acc[8][4] = {};
    for (int kc = 0; kc < 4; ++kc) {
        __syncthreads();
        for (int i = tx; i < 32 * 32; i += 256) {
            int r = i >> 5, c4 = i & 31;
            *(float4*)&ws_[r][c4 * 4] = ((const float4*)W)[(size_t)(kc * 32 + r) * 32 + c4];
        }
        __syncthreads();
        gemm_chunk(as_, ws_, r0, c0, kc * 32, acc);
    }
    float4 bb = *(const float4*)&bias[c0];
#pragma unroll
    for (int r = 0; r < 8; ++r) {
        int row = row0 + r0 + r;
        if (row < n) {
            float4 o4 = make_float4(acc[r][0] + bb.x, acc[r][1] + bb.y,
                                    acc[r][2] + bb.z, acc[r][3] + bb.w);
            ((float4*)out)[(size_t)row * 32 + cg] = o4;
        }
    }
}

// ---------------- K7: residual + LN2 (writes g_x2, g_h2) ----------------
__global__ void k_resid_ln2(const float* __restrict__ x, const float* __restrict__ alpha,
                            const float* __restrict__ g2, const float* __restrict__ b2,
                            int n) {
    int row = blockIdx.x * 8 + (threadIdx.x >> 5);
    if (row >= n) return;
    int lane = threadIdx.x & 31;
    float a = alpha[0];
    float4 xv = ((const float4*)x)[(size_t)row * 32 + lane];
    float4 av = ((const float4*)g_acc)[(size_t)row * 32 + lane];
    float4 sv = ((const float4*)g_skip)[(size_t)row * 32 + lane];
    float inv = 1.0f / (g_z[(size_t)row * HH + (lane >> 2)] + 1e-16f);
    float4 o;
    o.x = xv.x + a * (av.x * inv + sv.x);
    o.y = xv.y + a * (av.y * inv + sv.y);
    o.z = xv.z + a * (av.z * inv + sv.z);
    o.w = xv.w + a * (av.w * inv + sv.w);
    ((float4*)g_x2)[(size_t)row * 32 + lane] = o;
    float s  = o.x + o.y + o.z + o.w;
    float ss = fmaf(o.x, o.x, fmaf(o.y, o.y, fmaf(o.z, o.z, o.w * o.w)));
#pragma unroll
    for (int off = 16; off > 0; off >>= 1) {
        s  += __shfl_xor_sync(0xFFFFFFFFu, s, off);
        ss += __shfl_xor_sync(0xFFFFFFFFu, ss, off);
    }
    float mu  = s * (1.0f / 128.0f);
    float var = ss * (1.0f / 128.0f) - mu * mu;
    float r   = rsqrtf(var + 1e-5f);
    float4 gg = ((const float4*)g2)[lane];
    float4 bb = ((const float4*)b2)[lane];
    float4 h2;
    h2.x = (o.x - mu) * r * gg.x + bb.x;
    h2.y = (o.y - mu) * r * gg.y + bb.y;
    h2.z = (o.z - mu) * r * gg.z + bb.z;
    h2.w = (o.w - mu) * r * gg.w + bb.w;
    ((float4*)g_h2)[(size_t)row * 32 + lane] = h2;
}

// ---------------- K8: FFN1 u = silu(h2 @ W1 + b1) ----------------
__global__ void __launch_bounds__(256) k_ffn1(
        const float* __restrict__ W1, const float* __restrict__ b1, int n) {
    __shared__ float as_[64][128];
    __shared__ float ws_[32][128];
    int tx = threadIdx.x;
    int row0 = blockIdx.x * 64;
    int colbase = blockIdx.y * 128;
    for (int i = tx; i < 64 * 32; i += 256) {
        int r = i >> 5, c4 = i & 31;
        float4 val = (row0 + r < n) ? ((const float4*)g_h2)[(size_t)(row0 + r) * 32 + c4]
                                    : make_float4(0.f, 0.f, 0.f, 0.f);
        *(float4*)&as_[r][c4 * 4] = val;
    }
    int cg = tx & 31, rg = tx >> 5;
    int c0 = cg * 4, r0 = rg * 8;
    float acc[8][4] = {};
    for (int kc = 0; kc < 4; ++kc) {
        __syncthreads();
        for (int i = tx; i < 32 * 32; i += 256) {
            int r = i >> 5, c4 = i & 31;
            *(float4*)&ws_[r][c4 * 4] =
                ((const float4*)W1)[(size_t)(kc * 32 + r) * 128 + (colbase >> 2) + c4];
        }
        __syncthreads();
        gemm_chunk(as_, ws_, r0, c0, kc * 32, acc);
    }
    float4 bb = *(const float4*)&b1[colbase + c0];
#pragma unroll
    for (int r = 0; r < 8; ++r) {
        int row = row0 + r0 + r;
        if (row < n) {
            float v0 = acc[r][0] + bb.x, v1 = acc[r][1] + bb.y;
            float v2 = acc[r][2] + bb.z, v3 = acc[r][3] + bb.w;
            float4 o4;
            o4.x = v0 / (1.0f + __expf(-v0));
            o4.y = v1 / (1.0f + __expf(-v1));
            o4.z = v2 / (1.0f + __expf(-v2));
            o4.w = v3 / (1.0f + __expf(-v3));
            ((float4*)g_u)[(size_t)row * 128 + (colbase >> 2) + cg] = o4;
        }
    }
}

// ---------------- K9: FFN2 out = x2 + u @ W2 + b2 ----------------
__global__ void __launch_bounds__(256) k_ffn2(
        const float* __restrict__ W2, const float* __restrict__ b2,
        float* __restrict__ out, int n) {
    __shared__ float as_[64][128];
    __shared__ float ws_[32][128];
    int tx = threadIdx.x;
    int row0 = blockIdx.x * 64;
    int cg = tx & 31, rg = tx >> 5;
    int c0 = cg * 4, r0 = rg * 8;
    float acc[8][4] = {};
    for (int kc = 0; kc < 4; ++kc) {
        __syncthreads();
        for (int i = tx; i < 64 * 32; i += 256) {
            int r = i >> 5, c4 = i & 31;
            float4 val = (row0 + r < n)
                ? ((const float4*)g_u)[(size_t)(row0 + r) * 128 + kc * 32 + c4]
                : make_float4(0.f, 0.f, 0.f, 0.f);
            *(float4*)&as_[r][c4 * 4] = val;
        }
        for (int sub = 0; sub < 4; ++sub) {
            __syncthreads();
            for (int i = tx; i < 32 * 32; i += 256) {
                int r = i >> 5, c4 = i & 31;
                *(float4*)&ws_[r][c4 * 4] =
                    ((const float4*)W2)[(size_t)(kc * 128 + sub * 32 + r) * 32 + c4];
            }
            __syncthreads();
            gemm_chunk(as_, ws_, r0, c0, sub * 32, acc);
        }
    }
    float4 bb = *(const float4*)&b2[c0];
#pragma unroll
    for (int r = 0; r < 8; ++r) {
        int row = row0 + r0 + r;
        if (row < n) {
            float4 xv = ((const float4*)g_x2)[(size_t)row * 32 + cg];
            float4 o4 = make_float4(xv.x + acc[r][0] + bb.x, xv.y + acc[r][1] + bb.y,
                                    xv.z + acc[r][2] + bb.z, xv.w + acc[r][3] + bb.w);
            ((float4*)out)[(size_t)row * 32 + cg] = o4;
        }
    }
}

// ---------------- launch ----------------
extern "C" void kernel_launch(void* const* d_in, const int* in_sizes, int n_in,
                              void* d_out, int out_size) {
    const float* x      = (const float*)d_in[0];
    const float* eattr  = (const float*)d_in[1];
    const int*   ei     = (const int*)d_in[2];
    const float* Wq     = (const float*)d_in[3];
    const float* bq     = (const float*)d_in[4];
    const float* Wk     = (const float*)d_in[5];
    const float* bk     = (const float*)d_in[6];
    const float* Wv     = (const float*)d_in[7];
    const float* bv     = (const float*)d_in[8];
    const float* We     = (const float*)d_in[9];
    const float* Wskip  = (const float*)d_in[10];
    const float* bskip  = (const float*)d_in[11];
    const float* W1     = (const float*)d_in[12];
    const float* b1     = (const float*)d_in[13];
    const float* W2     = (const float*)d_in[14];
    const float* b2     = (const float*)d_in[15];
    const float* g1     = (const float*)d_in[16];
    const float* beta1  = (const float*)d_in[17];
    const float* g2     = (const float*)d_in[18];
    const float* beta2  = (const float*)d_in[19];
    const float* alpha  = (const float*)d_in[20];

    int n = in_sizes[0] / D;   // 50000
    int E = in_sizes[1] / D;   // 600000
    float* out = (float*)d_out;

    int rowTiles = (n + 63) / 64;

    static bool attr_set = false;
    if (!attr_set) {
        cudaFuncSetAttribute(k_edge_mma, cudaFuncAttributeMaxDynamicSharedMemorySize,
                             EDGE_SMEM_BYTES);
        attr_set = true;
    }

    k_ln1<<<(n + 7) / 8, 256>>>(x, g1, beta1, n);
    k_init<<<(n * D + 255) / 256, 256>>>(n);
    {
        dim3 grid(rowTiles, 4);
        k_node_gemm<<<grid, 256>>>(Wq, bq, Wk, bk, Wv, bv, Wskip, bskip, n);
    }
    k_edge_mma<<<(E + 127) / 128, 256, EDGE_SMEM_BYTES>>>(eattr, ei, We, E, n);
    k_resid_ln2<<<(n + 7) / 8, 256>>>(x, alpha, g2, beta2, n);
    {
        dim3 grid(rowTiles, 4);
        k_ffn1<<<grid, 256>>>(W1, b1, n);
    }
    k_ffn2<<<rowTiles, 256>>>(W2, b2, out, n);
}

// round 8
// speedup vs baseline: 1.3317x; 1.3317x over previous
#include <cuda_runtime.h>
#include <cuda_bf16.h>
#include <cstdint>

#define NN 50000
#define EE 600000
#define D 128
#define HH 8

// ---------------- scratch (device globals; no dynamic allocation) ----------------
__device__ float g_h   [(size_t)NN * D];
__device__ float g_q   [(size_t)NN * D];
__device__ float g_k   [(size_t)NN * D];
__device__ float g_v   [(size_t)NN * D];
__device__ float g_skip[(size_t)NN * D];
__device__ float g_z   [(size_t)NN * HH];
__device__ float g_acc [(size_t)NN * D];
__device__ float g_x2  [(size_t)NN * D];
__device__ float g_h2  [(size_t)NN * D];
__device__ float g_u   [(size_t)NN * 4 * D];

// preconverted transposed weights, bf16 hi/lo: [n][k] layouts
// offsets: Wq 0, Wk 16384, Wv 32768, Wskip 49152, We 65536, W1 81920, W2 147456
#define OFF_WQ 0
#define OFF_WE 65536
#define OFF_W1 81920
#define OFF_W2 147456
#define BT_TOTAL 212992
__device__ __nv_bfloat16 g_BtH[BT_TOTAL];
__device__ __nv_bfloat16 g_BtL[BT_TOTAL];

__device__ __forceinline__ int clampi(int v, int lo, int hi) {
    return v < lo ? lo : (v > hi ? hi : v);
}
__device__ __forceinline__ void red_v4(float* ptr, float a, float b, float c, float d) {
    asm volatile("red.global.v4.f32.add [%0], {%1,%2,%3,%4};"
                 :: "l"(ptr), "f"(a), "f"(b), "f"(c), "f"(d) : "memory");
}
__device__ __forceinline__ void red_f32(float* ptr, float a) {
    asm volatile("red.global.add.f32 [%0], %1;" :: "l"(ptr), "f"(a) : "memory");
}

// ---------------- arch-agnostic tensor-core helpers (sm_80+ PTX) ----------------
__device__ __forceinline__ uint32_t smem_u32(const void* p) {
    uint32_t a;
    asm("{ .reg .u64 t; cvta.to.shared.u64 t, %1; cvt.u32.u64 %0, t; }" : "=r"(a) : "l"(p));
    return a;
}
__device__ __forceinline__ void ldm_x4(uint32_t (&r)[4], uint32_t addr) {
    asm volatile("ldmatrix.sync.aligned.m8n8.x4.shared.b16 {%0,%1,%2,%3}, [%4];"
                 : "=r"(r[0]), "=r"(r[1]), "=r"(r[2]), "=r"(r[3]) : "r"(addr));
}
__device__ __forceinline__ void ldm_x2(uint32_t (&r)[2], uint32_t addr) {
    asm volatile("ldmatrix.sync.aligned.m8n8.x2.shared.b16 {%0,%1}, [%2];"
                 : "=r"(r[0]), "=r"(r[1]) : "r"(addr));
}
__device__ __forceinline__ void mma_bf16(float (&d)[4], const uint32_t (&a)[4],
                                         const uint32_t (&b)[2]) {
    asm volatile("mma.sync.aligned.m16n8k16.row.col.f32.bf16.bf16.f32 "
                 "{%0,%1,%2,%3}, {%4,%5,%6,%7}, {%8,%9}, {%0,%1,%2,%3};"
                 : "+f"(d[0]), "+f"(d[1]), "+f"(d[2]), "+f"(d[3])
                 : "r"(a[0]), "r"(a[1]), "r"(a[2]), "r"(a[3]), "r"(b[0]), "r"(b[1]));
}

// ---------------- K0: preconvert weights (transposed, bf16 hi/lo) ----------------
__global__ void k_preconv(const float* __restrict__ Wq, const float* __restrict__ Wk,
                          const float* __restrict__ Wv, const float* __restrict__ Ws,
                          const float* __restrict__ We, const float* __restrict__ W1,
                          const float* __restrict__ W2) {
    int i = blockIdx.x * 256 + threadIdx.x;
    if (i >= BT_TOTAL) return;
    float x;
    if (i < 65536) {
        int w = i >> 14, rem = i & 16383, nn = rem >> 7, kk = rem & 127;
        const float* W = (w == 0) ? Wq : (w == 1) ? Wk : (w == 2) ? Wv : Ws;
        x = W[kk * 128 + nn];
    } else if (i < 81920) {
        int rem = i - 65536, nn = rem >> 7, kk = rem & 127;
        x = We[kk * 128 + nn];
    } else if (i < 147456) {
        int rem = i - 81920, nn = rem >> 7, kk = rem & 127;
        x = W1[kk * 512 + nn];
    } else {
        int rem = i - 147456, nn = rem >> 9, kk = rem & 511;
        x = W2[kk * 128 + nn];
    }
    __nv_bfloat16 h = __float2bfloat16(x);
    g_BtH[i] = h;
    g_BtL[i] = __float2bfloat16(x - __bfloat162float(h));
}

// ---------------- generic dense GEMM: C[128 rows, 128 cols] via bf16 3-term mma ---
// A fp32 [M x As-strided]; Bt preconverted [n][k]; epi: 0=bias, 1=bias+silu, 2=bias+resid
#define DST 72
#define DENSE_SMEM 73728
__global__ void __launch_bounds__(256) k_dense(
        const float* __restrict__ A, int As,
        const __nv_bfloat16* __restrict__ BtHb, const __nv_bfloat16* __restrict__ BtLb,
        int K, const float* __restrict__ bias, float* __restrict__ Out, int Os,
        const float* __restrict__ resid, int epi, int M) {
    extern __shared__ char sm[];
    __nv_bfloat16* Ah = (__nv_bfloat16*)sm;
    __nv_bfloat16* Al = (__nv_bfloat16*)(sm + 18432);
    __nv_bfloat16* Bh = (__nv_bfloat16*)(sm + 36864);
    __nv_bfloat16* Bl = (__nv_bfloat16*)(sm + 55296);
    int tx = threadIdx.x, w = tx >> 5, lane = tx & 31;
    int row0 = blockIdx.x * 128, n0 = blockIdx.y * 128;
    const __nv_bfloat16* BH = BtHb + (size_t)n0 * K;
    const __nv_bfloat16* BL = BtLb + (size_t)n0 * K;
    float acc[16][4];
#pragma unroll
    for (int nt = 0; nt < 16; ++nt) {
        acc[nt][0] = 0.f; acc[nt][1] = 0.f; acc[nt][2] = 0.f; acc[nt][3] = 0.f;
    }
    int arow = w * 16 + (lane & 15);
    int acol = (lane >> 4) << 3;
    int brl = lane & 7, bcol = (lane & 8) ? 8 : 0;

    for (int kc = 0; kc < K; kc += 64) {
        __syncthreads();
        for (int i = tx; i < 2048; i += 256) {      // A chunk: 128 rows x 64 k
            int r = i >> 4, c4 = i & 15;
            float4 v = (row0 + r < M)
                ? *(const float4*)&A[(size_t)(row0 + r) * As + kc + c4 * 4]
                : make_float4(0.f, 0.f, 0.f, 0.f);
            __nv_bfloat16 h0 = __float2bfloat16(v.x), h1 = __float2bfloat16(v.y);
            __nv_bfloat16 h2 = __float2bfloat16(v.z), h3 = __float2bfloat16(v.w);
            __nv_bfloat162* ph = (__nv_bfloat162*)&Ah[r * DST + c4 * 4];
            ph[0] = __nv_bfloat162(h0, h1); ph[1] = __nv_bfloat162(h2, h3);
            __nv_bfloat162* pl = (__nv_bfloat162*)&Al[r * DST + c4 * 4];
            pl[0] = __nv_bfloat162(__float2bfloat16(v.x - __bfloat162float(h0)),
                                   __float2bfloat16(v.y - __bfloat162float(h1)));
            pl[1] = __nv_bfloat162(__float2bfloat16(v.z - __bfloat162float(h2)),
                                   __float2bfloat16(v.w - __bfloat162float(h3)));
        }
        for (int i = tx; i < 1024; i += 256) {      // B chunk: 128 n x 64 k
            int nr = i >> 3, k8 = (i & 7) * 8;
            *(uint4*)&Bh[nr * DST + k8] = *(const uint4*)&BH[(size_t)nr * K + kc + k8];
            *(uint4*)&Bl[nr * DST + k8] = *(const uint4*)&BL[(size_t)nr * K + kc + k8];
        }
        __syncthreads();
        for (int kt = 0; kt < 4; ++kt) {
            int k0 = kt * 16;
            uint32_t ah[4], al[4];
            ldm_x4(ah, smem_u32(&Ah[arow * DST + k0 + acol]));
            ldm_x4(al, smem_u32(&Al[arow * DST + k0 + acol]));
#pragma unroll
            for (int nt = 0; nt < 16; ++nt) {
                uint32_t bh[2], bl[2];
                ldm_x2(bh, smem_u32(&Bh[(nt * 8 + brl) * DST + k0 + bcol]));
                ldm_x2(bl, smem_u32(&Bl[(nt * 8 + brl) * DST + k0 + bcol]));
                mma_bf16(acc[nt], ah, bh);
                mma_bf16(acc[nt], ah, bl);
                mma_bf16(acc[nt], al, bh);
            }
        }
    }
    // epilogue straight from fragments
    int rbase = row0 + w * 16 + (lane >> 2);
    int cb = (lane & 3) * 2;
#pragma unroll
    for (int nt = 0; nt < 16; ++nt) {
        int c = n0 + nt * 8 + cb;
        float b0 = bias[c], b1 = bias[c + 1];
#pragma unroll
        for (int hrow = 0; hrow < 2; ++hrow) {
            int row = rbase + hrow * 8;
            if (row < M) {
                float v0 = acc[nt][hrow * 2 + 0] + b0;
                float v1 = acc[nt][hrow * 2 + 1] + b1;
                if (epi == 1) {
                    v0 = v0 / (1.0f + __expf(-v0));
                    v1 = v1 / (1.0f + __expf(-v1));
                } else if (epi == 2) {
                    v0 += resid[(size_t)row * 128 + c];
                    v1 += resid[(size_t)row * 128 + c + 1];
                }
                *(float2*)&Out[(size_t)row * Os + c] = make_float2(v0, v1);
            }
        }
    }
}

// ---------------- fused edge pass, N-halved (2 CTAs/SM) ----------------
#define EAST 136
#define ESM_B 69632
#define EDGE_SMEM (69632 + 34816)   // 104448
__global__ void __launch_bounds__(256) k_edge_mma(
        const float* __restrict__ ea_g, const int* __restrict__ ei, int E, int n) {
    extern __shared__ char sm[];
    __nv_bfloat16* Ah = (__nv_bfloat16*)sm;
    __nv_bfloat16* Al = (__nv_bfloat16*)(sm + 34816);
    __nv_bfloat16* Bh = (__nv_bfloat16*)(sm + ESM_B);
    __nv_bfloat16* Bl = (__nv_bfloat16*)(sm + ESM_B + 17408);
    float* C = (float*)(sm + ESM_B);
    const __nv_bfloat16* WeTH = g_BtH + OFF_WE;
    const __nv_bfloat16* WeTL = g_BtL + OFF_WE;
    int tx = threadIdx.x, w = tx >> 5, lane = tx & 31;
    int e0 = blockIdx.x * 128;

    // convert EA tile -> bf16 hi/lo
    for (int idx = tx; idx < 4096; idx += 256) {
        int r = idx >> 5, c4 = idx & 31;
        float4 v = (e0 + r < E) ? ((const float4*)ea_g)[(size_t)(e0 + r) * 32 + c4]
                                : make_float4(0.f, 0.f, 0.f, 0.f);
        __nv_bfloat16 h0 = __float2bfloat16(v.x), h1 = __float2bfloat16(v.y);
        __nv_bfloat16 h2 = __float2bfloat16(v.z), h3 = __float2bfloat16(v.w);
        __nv_bfloat162* ph = (__nv_bfloat162*)&Ah[r * EAST + c4 * 4];
        ph[0] = __nv_bfloat162(h0, h1); ph[1] = __nv_bfloat162(h2, h3);
        __nv_bfloat162* pl = (__nv_bfloat162*)&Al[r * EAST + c4 * 4];
        pl[0] = __nv_bfloat162(__float2bfloat16(v.x - __bfloat162float(h0)),
                               __float2bfloat16(v.y - __bfloat162float(h1)));
        pl[1] = __nv_bfloat162(__float2bfloat16(v.z - __bfloat162float(h2)),
                               __float2bfloat16(v.w - __bfloat162float(h3)));
    }
    int arow = w * 16 + (lane & 15);
    int acol = (lane >> 4) << 3;
    int brl = lane & 7, bcol = (lane & 8) ? 8 : 0;
    int row = tx & 127, seg = tx >> 7;
    int e = e0 + row;

    for (int h = 0; h < 2; ++h) {
        if (h) __syncthreads();                     // epilogue(0) done with C
        for (int i = tx; i < 1024; i += 256) {      // B half: 64 n x 128 k
            int nr = i >> 4, k8 = (i & 15) * 8;
            *(uint4*)&Bh[nr * EAST + k8] = *(const uint4*)&WeTH[(size_t)(h * 64 + nr) * 128 + k8];
            *(uint4*)&Bl[nr * EAST + k8] = *(const uint4*)&WeTL[(size_t)(h * 64 + nr) * 128 + k8];
        }
        __syncthreads();
        float acc[8][4];
#pragma unroll
        for (int nt = 0; nt < 8; ++nt) {
            acc[nt][0] = 0.f; acc[nt][1] = 0.f; acc[nt][2] = 0.f; acc[nt][3] = 0.f;
        }
        for (int kt = 0; kt < 8; ++kt) {
            int k0 = kt * 16;
            uint32_t ah[4], al[4];
            ldm_x4(ah, smem_u32(&Ah[arow * EAST + k0 + acol]));
            ldm_x4(al, smem_u32(&Al[arow * EAST + k0 + acol]));
#pragma unroll
            for (int nt = 0; nt < 8; ++nt) {
                uint32_t bh[2], bl[2];
                ldm_x2(bh, smem_u32(&Bh[(nt * 8 + brl) * EAST + k0 + bcol]));
                ldm_x2(bl, smem_u32(&Bl[(nt * 8 + brl) * EAST + k0 + bcol]));
                mma_bf16(acc[nt], ah, bh);
                mma_bf16(acc[nt], ah, bl);
                mma_bf16(acc[nt], al, bh);
            }
        }
        __syncthreads();                            // mma done reading B
        {
            int r0 = w * 16 + (lane >> 2), cb = (lane & 3) * 2;
#pragma unroll
            for (int nt = 0; nt < 8; ++nt) {
                int lc = nt * 8 + cb;
                C[r0 * 68 + lc] = acc[nt][0];
                C[r0 * 68 + lc + 1] = acc[nt][1];
                C[(r0 + 8) * 68 + lc] = acc[nt][2];
                C[(r0 + 8) * 68 + lc + 1] = acc[nt][3];
            }
        }
        __syncthreads();
        if (e < E) {
            int src = clampi(ei[e], 0, n - 1);
            int dst = clampi(ei[(size_t)E + e], 0, n - 1);
            const float4* kp = (const float4*)&g_k[(size_t)src * D];
            const float4* vp = (const float4*)&g_v[(size_t)src * D];
            const float4* qp = (const float4*)&g_q[(size_t)dst * D];
#pragma unroll
            for (int hh = 0; hh < 2; ++hh) {
                int lcb = seg * 32 + hh * 16;       // local col within the 64-half
                int gc = h * 64 + lcb;              // global col
                float logit = 0.f;
                float pv[16];
#pragma unroll
                for (int j = 0; j < 4; ++j) {
                    float4 ee = *(const float4*)&C[row * 68 + lcb + j * 4];
                    float4 kq = kp[(gc >> 2) + j];
                    float4 qq = qp[(gc >> 2) + j];
                    float4 vv = vp[(gc >> 2) + j];
                    logit = fmaf(qq.x, kq.x + ee.x, logit);
                    logit = fmaf(qq.y, kq.y + ee.y, logit);
                    logit = fmaf(qq.z, kq.z + ee.z, logit);
                    logit = fmaf(qq.w, kq.w + ee.w, logit);
                    pv[j * 4 + 0] = vv.x + ee.x;
                    pv[j * 4 + 1] = vv.y + ee.y;
                    pv[j * 4 + 2] = vv.z + ee.z;
                    pv[j * 4 + 3] = vv.w + ee.w;
                }
                float p = __expf(logit * 0.25f);    // 1/sqrt(16); shift-invariant
#pragma unroll
                for (int j = 0; j < 4; ++j)
                    red_v4(&g_acc[(size_t)dst * D + gc + j * 4],
                           p * pv[j * 4 + 0], p * pv[j * 4 + 1],
                           p * pv[j * 4 + 2], p * pv[j * 4 + 3]);
                red_f32(&g_z[(size_t)dst * HH + (gc >> 4)], p);
            }
        }
    }
}

// ---------------- K1: LayerNorm1 ----------------
__global__ void k_ln1(const float* __restrict__ x, const float* __restrict__ g,
                      const float* __restrict__ b, int n) {
    int row = blockIdx.x * 8 + (threadIdx.x >> 5);
    if (row >= n) return;
    int lane = threadIdx.x & 31;
    float4 v = ((const float4*)x)[(size_t)row * 32 + lane];
    float s  = v.x + v.y + v.z + v.w;
    float ss = fmaf(v.x, v.x, fmaf(v.y, v.y, fmaf(v.z, v.z, v.w * v.w)));
#pragma unroll
    for (int o = 16; o > 0; o >>= 1) {
        s  += __shfl_xor_sync(0xFFFFFFFFu, s, o);
        ss += __shfl_xor_sync(0xFFFFFFFFu, ss, o);
    }
    float mu  = s * (1.0f / 128.0f);
    float var = ss * (1.0f / 128.0f) - mu * mu;
    float r   = rsqrtf(var + 1e-5f);
    float4 gg = ((const float4*)g)[lane];
    float4 bb = ((const float4*)b)[lane];
    float4 o4;
    o4.x = (v.x - mu) * r * gg.x + bb.x;
    o4.y = (v.y - mu) * r * gg.y + bb.y;
    o4.z = (v.z - mu) * r * gg.z + bb.z;
    o4.w = (v.w - mu) * r * gg.w + bb.w;
    ((float4*)g_h)[(size_t)row * 32 + lane] = o4;
}

// ---------------- K2: init segment buffers ----------------
__global__ void k_init(int n) {
    int i = blockIdx.x * blockDim.x + threadIdx.x;
    if (i < n * HH) g_z[i] = 0.0f;
    if (i < n * D)  g_acc[i] = 0.0f;
}

// ---------------- K7: residual + LN2 ----------------
__global__ void k_resid_ln2(const float* __restrict__ x, const float* __restrict__ alpha,
                            const float* __restrict__ g2, const float* __restrict__ b2,
                            int n) {
    int row = blockIdx.x * 8 + (threadIdx.x >> 5);
    if (row >= n) return;
    int lane = threadIdx.x & 31;
    float a = alpha[0];
    float4 xv = ((const float4*)x)[(size_t)row * 32 + lane];
    float4 av = ((const float4*)g_acc)[(size_t)row * 32 + lane];
    float4 sv = ((const float4*)g_skip)[(size_t)row * 32 + lane];
    float inv = 1.0f / (g_z[(size_t)row * HH + (lane >> 2)] + 1e-16f);
    float4 o;
    o.x = xv.x + a * (av.x * inv + sv.x);
    o.y = xv.y + a * (av.y * inv + sv.y);
    o.z = xv.z + a * (av.z * inv + sv.z);
    o.w = xv.w + a * (av.w * inv + sv.w);
    ((float4*)g_x2)[(size_t)row * 32 + lane] = o;
    float s  = o.x + o.y + o.z + o.w;
    float ss = fmaf(o.x, o.x, fmaf(o.y, o.y, fmaf(o.z, o.z, o.w * o.w)));
#pragma unroll
    for (int off = 16; off > 0; off >>= 1) {
        s  += __shfl_xor_sync(0xFFFFFFFFu, s, off);
        ss += __shfl_xor_sync(0xFFFFFFFFu, ss, off);
    }
    float mu  = s * (1.0f / 128.0f);
    float var = ss * (1.0f / 128.0f) - mu * mu;
    float r   = rsqrtf(var + 1e-5f);
    float4 gg = ((const float4*)g2)[lane];
    float4 bb = ((const float4*)b2)[lane];
    float4 h2;
    h2.x = (o.x - mu) * r * gg.x + bb.x;
    h2.y = (o.y - mu) * r * gg.y + bb.y;
    h2.z = (o.z - mu) * r * gg.z + bb.z;
    h2.w = (o.w - mu) * r * gg.w + bb.w;
    ((float4*)g_h2)[(size_t)row * 32 + lane] = h2;
}

// ---------------- launch ----------------
extern "C" void kernel_launch(void* const* d_in, const int* in_sizes, int n_in,
                              void* d_out, int out_size) {
    const float* x      = (const float*)d_in[0];
    const float* eattr  = (const float*)d_in[1];
    const int*   ei     = (const int*)d_in[2];
    const float* Wq     = (const float*)d_in[3];
    const float* bq     = (const float*)d_in[4];
    const float* Wk     = (const float*)d_in[5];
    const float* bk     = (const float*)d_in[6];
    const float* Wv     = (const float*)d_in[7];
    const float* bv     = (const float*)d_in[8];
    const float* We     = (const float*)d_in[9];
    const float* Wskip  = (const float*)d_in[10];
    const float* bskip  = (const float*)d_in[11];
    const float* W1     = (const float*)d_in[12];
    const float* b1     = (const float*)d_in[13];
    const float* W2     = (const float*)d_in[14];
    const float* b2     = (const float*)d_in[15];
    const float* g1     = (const float*)d_in[16];
    const float* beta1  = (const float*)d_in[17];
    const float* g2     = (const float*)d_in[18];
    const float* beta2  = (const float*)d_in[19];
    const float* alpha  = (const float*)d_in[20];

    int n = in_sizes[0] / D;   // 50000
    int E = in_sizes[1] / D;   // 600000
    float* out = (float*)d_out;

    int rowTiles = (n + 127) / 128;       // 391
    int edgeTiles = (E + 127) / 128;      // 4688

    static bool attr_set = false;
    if (!attr_set) {
        cudaFuncSetAttribute(k_edge_mma, cudaFuncAttributeMaxDynamicSharedMemorySize,
                             EDGE_SMEM);
        cudaFuncSetAttribute(k_dense, cudaFuncAttributeMaxDynamicSharedMemorySize,
                             DENSE_SMEM);
        attr_set = true;
    }

    float *BtH, *BtL;   // raw device pointers to the __device__ arrays via symbols
    // (we index g_BtH/g_BtL inside kernels; host just passes offsets)

    k_preconv<<<(BT_TOTAL + 255) / 256, 256>>>(Wq, Wk, Wv, Wskip, We, W1, W2);
    k_ln1<<<(n + 7) / 8, 256>>>(x, g1, beta1, n);
    k_init<<<(n * D + 255) / 256, 256>>>(n);

    // node projections: q,k,v,skip (K=128, epi=bias)
    {
        // device-symbol addresses aren't needed host-side: k_dense takes pointers,
        // so fetch them once via cudaGetSymbolAddress-free trick: use a tiny kernel?
        // Simpler: k_dense reads from g_BtH via passed offset pointers obtained here.
        static __nv_bfloat16 *pH = nullptr, *pL = nullptr;
        if (!pH) {
            cudaGetSymbolAddress((void**)&pH, g_BtH);
            cudaGetSymbolAddress((void**)&pL, g_BtL);
        }
        static float *pq = nullptr, *pk = nullptr, *pv = nullptr, *ps = nullptr,
                     *ph = nullptr, *ph2 = nullptr, *pu = nullptr, *px2 = nullptr;
        if (!pq) {
            cudaGetSymbolAddress((void**)&pq, g_q);
            cudaGetSymbolAddress((void**)&pk, g_k);
            cudaGetSymbolAddress((void**)&pv, g_v);
            cudaGetSymbolAddress((void**)&ps, g_skip);
            cudaGetSymbolAddress((void**)&ph, g_h);
            cudaGetSymbolAddress((void**)&ph2, g_h2);
            cudaGetSymbolAddress((void**)&pu, g_u);
            cudaGetSymbolAddress((void**)&px2, g_x2);
        }
        dim3 g1d(rowTiles, 1);
        k_dense<<<g1d, 256, DENSE_SMEM>>>(ph, 128, pH + OFF_WQ, pL + OFF_WQ, 128,
                                          bq, pq, 128, nullptr, 0, n);
        k_dense<<<g1d, 256, DENSE_SMEM>>>(ph, 128, pH + OFF_WQ + 16384, pL + OFF_WQ + 16384,
                                          128, bk, pk, 128, nullptr, 0, n);
        k_dense<<<g1d, 256, DENSE_SMEM>>>(ph, 128, pH + OFF_WQ + 32768, pL + OFF_WQ + 32768,
                                          128, bv, pv, 128, nullptr, 0, n);
        k_dense<<<g1d, 256, DENSE_SMEM>>>(ph, 128, pH + OFF_WQ + 49152, pL + OFF_WQ + 49152,
                                          128, bskip, ps, 128, nullptr, 0, n);

        k_edge_mma<<<edgeTiles, 256, EDGE_SMEM>>>(eattr, ei, E, n);
        k_resid_ln2<<<(n + 7) / 8, 256>>>(x, alpha, g2, beta2, n);

        dim3 gff1(rowTiles, 4);
        k_dense<<<gff1, 256, DENSE_SMEM>>>(ph2, 128, pH + OFF_W1, pL + OFF_W1, 128,
                                           b1, pu, 512, nullptr, 1, n);
        k_dense<<<g1d, 256, DENSE_SMEM>>>(pu, 512, pH + OFF_W2, pL + OFF_W2, 512,
                                          b2, out, 128, px2, 2, n);
    }
}

// round 9
// speedup vs baseline: 1.5085x; 1.1327x over previous
#include <cuda_runtime.h>
#include <cuda_bf16.h>
#include <cstdint>

#define NN 50000
#define EE 600000
#define D 128
#define HH 8

// ---------------- scratch (device globals) ----------------
__device__ __nv_bfloat16 g_hH [(size_t)NN * D];
__device__ __nv_bfloat16 g_hL [(size_t)NN * D];
__device__ float g_qkvs[(size_t)NN * 512];         // q|k|v|skip
__device__ float g_z   [(size_t)NN * HH];
__device__ float g_acc [(size_t)NN * D];
__device__ float g_x2  [(size_t)NN * D];
__device__ __nv_bfloat16 g_h2H[(size_t)NN * D];
__device__ __nv_bfloat16 g_h2L[(size_t)NN * D];
__device__ __nv_bfloat16 g_uH [(size_t)NN * 4 * D];
__device__ __nv_bfloat16 g_uL [(size_t)NN * 4 * D];

// preconverted transposed weights, bf16 hi/lo, [n][k]
#define OFF_WQ 0
#define OFF_WE 65536
#define OFF_W1 81920
#define OFF_W2 147456
#define BT_TOTAL 212992
__device__ __nv_bfloat16 g_BtH[BT_TOTAL];
__device__ __nv_bfloat16 g_BtL[BT_TOTAL];
__device__ float g_bqkvs[512];

__device__ __forceinline__ int clampi(int v, int lo, int hi) {
    return v < lo ? lo : (v > hi ? hi : v);
}
__device__ __forceinline__ void red_v2(float* ptr, float a, float b) {
    asm volatile("red.global.v2.f32.add [%0], {%1,%2};"
                 :: "l"(ptr), "f"(a), "f"(b) : "memory");
}
__device__ __forceinline__ void red_f32(float* ptr, float a) {
    asm volatile("red.global.add.f32 [%0], %1;" :: "l"(ptr), "f"(a) : "memory");
}

// ---------------- mma helpers (sm_80+ PTX, arch-agnostic) ----------------
__device__ __forceinline__ uint32_t smem_u32(const void* p) {
    uint32_t a;
    asm("{ .reg .u64 t; cvta.to.shared.u64 t, %1; cvt.u32.u64 %0, t; }" : "=r"(a) : "l"(p));
    return a;
}
__device__ __forceinline__ void ldm_x4(uint32_t (&r)[4], uint32_t addr) {
    asm volatile("ldmatrix.sync.aligned.m8n8.x4.shared.b16 {%0,%1,%2,%3}, [%4];"
                 : "=r"(r[0]), "=r"(r[1]), "=r"(r[2]), "=r"(r[3]) : "r"(addr));
}
__device__ __forceinline__ void ldm_x2(uint32_t (&r)[2], uint32_t addr) {
    asm volatile("ldmatrix.sync.aligned.m8n8.x2.shared.b16 {%0,%1}, [%2];"
                 : "=r"(r[0]), "=r"(r[1]) : "r"(addr));
}
__device__ __forceinline__ void mma_bf16(float (&d)[4], const uint32_t (&a)[4],
                                         const uint32_t (&b)[2]) {
    asm volatile("mma.sync.aligned.m16n8k16.row.col.f32.bf16.bf16.f32 "
                 "{%0,%1,%2,%3}, {%4,%5,%6,%7}, {%8,%9}, {%0,%1,%2,%3};"
                 : "+f"(d[0]), "+f"(d[1]), "+f"(d[2]), "+f"(d[3])
                 : "r"(a[0]), "r"(a[1]), "r"(a[2]), "r"(a[3]), "r"(b[0]), "r"(b[1]));
}

// ---------------- K0: preconvert weights ----------------
__global__ void k_preconv(const float* __restrict__ Wq, const float* __restrict__ Wk,
                          const float* __restrict__ Wv, const float* __restrict__ Ws,
                          const float* __restrict__ We, const float* __restrict__ W1,
                          const float* __restrict__ W2) {
    int i = blockIdx.x * 256 + threadIdx.x;
    if (i >= BT_TOTAL) return;
    float x;
    if (i < 65536) {
        int w = i >> 14, rem = i & 16383, nn = rem >> 7, kk = rem & 127;
        const float* W = (w == 0) ? Wq : (w == 1) ? Wk : (w == 2) ? Wv : Ws;
        x = W[kk * 128 + nn];
    } else if (i < 81920) {
        int rem = i - 65536, nn = rem >> 7, kk = rem & 127;
        x = We[kk * 128 + nn];
    } else if (i < 147456) {
        int rem = i - 81920, nn = rem >> 7, kk = rem & 127;
        x = W1[kk * 512 + nn];
    } else {
        int rem = i - 147456, nn = rem >> 9, kk = rem & 511;
        x = W2[kk * 128 + nn];
    }
    __nv_bfloat16 h = __float2bfloat16(x);
    g_BtH[i] = h;
    g_BtL[i] = __float2bfloat16(x - __bfloat162float(h));
}
__global__ void k_bias(const float* __restrict__ bq, const float* __restrict__ bk,
                       const float* __restrict__ bv, const float* __restrict__ bs) {
    int i = threadIdx.x + blockIdx.x * 256;
    if (i >= 512) return;
    int w = i >> 7, j = i & 127;
    g_bqkvs[i] = (w == 0) ? bq[j] : (w == 1) ? bk[j] : (w == 2) ? bv[j] : bs[j];
}

// ---------------- generic dense GEMM with bf16 hi/lo inputs ----------------
#define DST 72
#define DENSE_SMEM 73728
__global__ void __launch_bounds__(256) k_dense_bf(
        const __nv_bfloat16* __restrict__ AH, const __nv_bfloat16* __restrict__ AL, int As,
        const __nv_bfloat16* __restrict__ BtHb, const __nv_bfloat16* __restrict__ BtLb,
        int K, const float* __restrict__ bias,
        float* __restrict__ Out, __nv_bfloat16* __restrict__ OutH,
        __nv_bfloat16* __restrict__ OutL, int Os,
        const float* __restrict__ resid, int epi, int M) {
    extern __shared__ char sm[];
    __nv_bfloat16* Ah = (__nv_bfloat16*)sm;
    __nv_bfloat16* Al = (__nv_bfloat16*)(sm + 18432);
    __nv_bfloat16* Bh = (__nv_bfloat16*)(sm + 36864);
    __nv_bfloat16* Bl = (__nv_bfloat16*)(sm + 55296);
    int tx = threadIdx.x, w = tx >> 5, lane = tx & 31;
    int row0 = blockIdx.x * 128, n0 = blockIdx.y * 128;
    const __nv_bfloat16* BH = BtHb + (size_t)n0 * K;
    const __nv_bfloat16* BL = BtLb + (size_t)n0 * K;
    float acc[16][4];
#pragma unroll
    for (int nt = 0; nt < 16; ++nt) {
        acc[nt][0] = 0.f; acc[nt][1] = 0.f; acc[nt][2] = 0.f; acc[nt][3] = 0.f;
    }
    int arow = w * 16 + (lane & 15);
    int acol = (lane >> 4) << 3;
    int brl = lane & 7, bcol = (lane & 8) ? 8 : 0;

    for (int kc = 0; kc < K; kc += 64) {
        __syncthreads();
        for (int i = tx; i < 2048; i += 256) {       // A: 128 rows x 64 k, hi+lo
            int half = i >> 10, j = i & 1023;
            int r = j >> 3, k8 = (j & 7) * 8;
            const __nv_bfloat16* s = half ? AL : AH;
            __nv_bfloat16* d = half ? Al : Ah;
            uint4 val = (row0 + r < M)
                ? *(const uint4*)&s[(size_t)(row0 + r) * As + kc + k8]
                : make_uint4(0u, 0u, 0u, 0u);
            *(uint4*)&d[r * DST + k8] = val;
        }
        for (int i = tx; i < 2048; i += 256) {       // B: 128 n x 64 k, hi+lo
            int half = i >> 10, j = i & 1023;
            int nr = j >> 3, k8 = (j & 7) * 8;
            const __nv_bfloat16* s = half ? BL : BH;
            __nv_bfloat16* d = half ? Bl : Bh;
            *(uint4*)&d[nr * DST + k8] = *(const uint4*)&s[(size_t)nr * K + kc + k8];
        }
        __syncthreads();
        for (int kt = 0; kt < 4; ++kt) {
            int k0 = kt * 16;
            uint32_t ah[4], al[4];
            ldm_x4(ah, smem_u32(&Ah[arow * DST + k0 + acol]));
            ldm_x4(al, smem_u32(&Al[arow * DST + k0 + acol]));
#pragma unroll
            for (int nt = 0; nt < 16; ++nt) {
                uint32_t bh[2], bl[2];
                ldm_x2(bh, smem_u32(&Bh[(nt * 8 + brl) * DST + k0 + bcol]));
                ldm_x2(bl, smem_u32(&Bl[(nt * 8 + brl) * DST + k0 + bcol]));
                mma_bf16(acc[nt], ah, bh);
                mma_bf16(acc[nt], ah, bl);
                mma_bf16(acc[nt], al, bh);
            }
        }
    }
    int rbase = row0 + w * 16 + (lane >> 2);
    int cb = (lane & 3) * 2;
#pragma unroll
    for (int nt = 0; nt < 16; ++nt) {
        int c = n0 + nt * 8 + cb;
        float b0 = bias[c], b1 = bias[c + 1];
#pragma unroll
        for (int hr = 0; hr < 2; ++hr) {
            int row = rbase + hr * 8;
            if (row < M) {
                float v0 = acc[nt][hr * 2 + 0] + b0;
                float v1 = acc[nt][hr * 2 + 1] + b1;
                if (epi == 1) {                       // silu -> bf16 hi/lo out
                    v0 = v0 / (1.0f + __expf(-v0));
                    v1 = v1 / (1.0f + __expf(-v1));
                    __nv_bfloat16 h0 = __float2bfloat16(v0);
                    __nv_bfloat16 h1 = __float2bfloat16(v1);
                    *(__nv_bfloat162*)&OutH[(size_t)row * Os + c] = __nv_bfloat162(h0, h1);
                    *(__nv_bfloat162*)&OutL[(size_t)row * Os + c] =
                        __nv_bfloat162(__float2bfloat16(v0 - __bfloat162float(h0)),
                                       __float2bfloat16(v1 - __bfloat162float(h1)));
                } else {
                    if (epi == 2) {
                        v0 += resid[(size_t)row * 128 + c];
                        v1 += resid[(size_t)row * 128 + c + 1];
                    }
                    *(float2*)&Out[(size_t)row * Os + c] = make_float2(v0, v1);
                }
            }
        }
    }
}

// ---------------- fused edge pass: register epilogue, no C spill ----------------
#define EAST 136
#define EDGE_SMEM 104448
__global__ void __launch_bounds__(256) k_edge_mma(
        const float* __restrict__ ea_g, const int* __restrict__ ei, int E, int n) {
    extern __shared__ char sm[];
    __nv_bfloat16* Ah = (__nv_bfloat16*)sm;                    // 34816
    __nv_bfloat16* Al = (__nv_bfloat16*)(sm + 34816);          // 34816
    __nv_bfloat16* Bh = (__nv_bfloat16*)(sm + 69632);          // 17408
    __nv_bfloat16* Bl = (__nv_bfloat16*)(sm + 87040);          // 17408
    const __nv_bfloat16* WeTH = g_BtH + OFF_WE;
    const __nv_bfloat16* WeTL = g_BtL + OFF_WE;
    int tx = threadIdx.x, w = tx >> 5, lane = tx & 31;
    int e0 = blockIdx.x * 128;

    // convert EA tile fp32 -> bf16 hi/lo
    for (int idx = tx; idx < 4096; idx += 256) {
        int r = idx >> 5, c4 = idx & 31;
        float4 v = (e0 + r < E) ? ((const float4*)ea_g)[(size_t)(e0 + r) * 32 + c4]
                                : make_float4(0.f, 0.f, 0.f, 0.f);
        __nv_bfloat16 h0 = __float2bfloat16(v.x), h1 = __float2bfloat16(v.y);
        __nv_bfloat16 h2 = __float2bfloat16(v.z), h3 = __float2bfloat16(v.w);
        __nv_bfloat162* ph = (__nv_bfloat162*)&Ah[r * EAST + c4 * 4];
        ph[0] = __nv_bfloat162(h0, h1); ph[1] = __nv_bfloat162(h2, h3);
        __nv_bfloat162* pl = (__nv_bfloat162*)&Al[r * EAST + c4 * 4];
        pl[0] = __nv_bfloat162(__float2bfloat16(v.x - __bfloat162float(h0)),
                               __float2bfloat16(v.y - __bfloat162float(h1)));
        pl[1] = __nv_bfloat162(__float2bfloat16(v.z - __bfloat162float(h2)),
                               __float2bfloat16(v.w - __bfloat162float(h3)));
    }
    int arow = w * 16 + (lane & 15);
    int acol = (lane >> 4) << 3;
    int brl = lane & 7, bcol = (lane & 8) ? 8 : 0;

    float acc[16][4];
#pragma unroll
    for (int nt = 0; nt < 16; ++nt) {
        acc[nt][0] = 0.f; acc[nt][1] = 0.f; acc[nt][2] = 0.f; acc[nt][3] = 0.f;
    }
    for (int h = 0; h < 2; ++h) {
        if (h) __syncthreads();       // all warps done reading B(0)
        for (int i = tx; i < 2048; i += 256) {       // B half: 64 n x 128 k, hi+lo
            int half = i >> 10, j = i & 1023;
            int nr = j >> 4, k8 = (j & 15) * 8;
            const __nv_bfloat16* s = half ? WeTL : WeTH;
            __nv_bfloat16* d = half ? Bl : Bh;
            *(uint4*)&d[nr * EAST + k8] = *(const uint4*)&s[(size_t)(h * 64 + nr) * 128 + k8];
        }
        __syncthreads();
        for (int kt = 0; kt < 8; ++kt) {
            int k0 = kt * 16;
            uint32_t ah[4], al[4];
            ldm_x4(ah, smem_u32(&Ah[arow * EAST + k0 + acol]));
            ldm_x4(al, smem_u32(&Al[arow * EAST + k0 + acol]));
#pragma unroll
            for (int nt = 0; nt < 8; ++nt) {
                uint32_t bh[2], bl[2];
                ldm_x2(bh, smem_u32(&Bh[(nt * 8 + brl) * EAST + k0 + bcol]));
                ldm_x2(bl, smem_u32(&Bl[(nt * 8 + brl) * EAST + k0 + bcol]));
                mma_bf16(acc[h * 8 + nt], ah, bh);
                mma_bf16(acc[h * 8 + nt], ah, bl);
                mma_bf16(acc[h * 8 + nt], al, bh);
            }
        }
    }

    // register epilogue: quad (4 lanes) owns a row; head = 2 adjacent nt tiles
    int cb = (lane & 3) * 2;
#pragma unroll
    for (int rr = 0; rr < 2; ++rr) {
        int row = w * 16 + (lane >> 2) + rr * 8;
        int e = e0 + row;
        bool ok = (e < E);
        int ee = ok ? e : E - 1;
        int src = clampi(ei[ee], 0, n - 1);
        int dst = clampi(ei[(size_t)E + ee], 0, n - 1);
        const float* qb = &g_qkvs[(size_t)dst * 512];
        const float* kb = &g_qkvs[(size_t)src * 512 + 128];
        const float* vb = &g_qkvs[(size_t)src * 512 + 256];
#pragma unroll
        for (int hd = 0; hd < 8; ++hd) {
            float part = 0.f;
            float pv[4];
#pragma unroll
            for (int t = 0; t < 2; ++t) {
                int gnt = hd * 2 + t;
                int gc = gnt * 8 + cb;
                float e0v = acc[gnt][rr * 2 + 0], e1v = acc[gnt][rr * 2 + 1];
                float2 kq = *(const float2*)&kb[gc];
                float2 qq = *(const float2*)&qb[gc];
                float2 vv = *(const float2*)&vb[gc];
                part = fmaf(qq.x, kq.x + e0v, part);
                part = fmaf(qq.y, kq.y + e1v, part);
                pv[t * 2 + 0] = vv.x + e0v;
                pv[t * 2 + 1] = vv.y + e1v;
            }
            part += __shfl_xor_sync(0xFFFFFFFFu, part, 1);
            part += __shfl_xor_sync(0xFFFFFFFFu, part, 2);
            float p = __expf(part * 0.25f);   // 1/sqrt(16); shift-invariant softmax
            if (ok) {
#pragma unroll
                for (int t = 0; t < 2; ++t) {
                    int gc = (hd * 2 + t) * 8 + cb;
                    red_v2(&g_acc[(size_t)dst * 128 + gc], p * pv[t * 2], p * pv[t * 2 + 1]);
                }
                if ((lane & 3) == 0) red_f32(&g_z[(size_t)dst * HH + hd], p);
            }
        }
    }
}

// ---------------- K1: LayerNorm1 -> bf16 hi/lo ----------------
__global__ void k_ln1(const float* __restrict__ x, const float* __restrict__ g,
                      const float* __restrict__ b, int n) {
    int row = blockIdx.x * 8 + (threadIdx.x >> 5);
    if (row >= n) return;
    int lane = threadIdx.x & 31;
    float4 v = ((const float4*)x)[(size_t)row * 32 + lane];
    float s  = v.x + v.y + v.z + v.w;
    float ss = fmaf(v.x, v.x, fmaf(v.y, v.y, fmaf(v.z, v.z, v.w * v.w)));
#pragma unroll
    for (int o = 16; o > 0; o >>= 1) {
        s  += __shfl_xor_sync(0xFFFFFFFFu, s, o);
        ss += __shfl_xor_sync(0xFFFFFFFFu, ss, o);
    }
    float mu  = s * (1.0f / 128.0f);
    float var = ss * (1.0f / 128.0f) - mu * mu;
    float r   = rsqrtf(var + 1e-5f);
    float4 gg = ((const float4*)g)[lane];
    float4 bb = ((const float4*)b)[lane];
    float o0 = (v.x - mu) * r * gg.x + bb.x;
    float o1 = (v.y - mu) * r * gg.y + bb.y;
    float o2 = (v.z - mu) * r * gg.z + bb.z;
    float o3 = (v.w - mu) * r * gg.w + bb.w;
    __nv_bfloat16 h0 = __float2bfloat16(o0), h1 = __float2bfloat16(o1);
    __nv_bfloat16 h2 = __float2bfloat16(o2), h3 = __float2bfloat16(o3);
    size_t base = (size_t)row * 128 + lane * 4;
    *(__nv_bfloat162*)&g_hH[base]     = __nv_bfloat162(h0, h1);
    *(__nv_bfloat162*)&g_hH[base + 2] = __nv_bfloat162(h2, h3);
    *(__nv_bfloat162*)&g_hL[base]     =
        __nv_bfloat162(__float2bfloat16(o0 - __bfloat162float(h0)),
                       __float2bfloat16(o1 - __bfloat162float(h1)));
    *(__nv_bfloat162*)&g_hL[base + 2] =
        __nv_bfloat162(__float2bfloat16(o2 - __bfloat162float(h2)),
                       __float2bfloat16(o3 - __bfloat162float(h3)));
}

// ---------------- K2: init segment buffers ----------------
__global__ void k_init(int n) {
    int i = blockIdx.x * blockDim.x + threadIdx.x;
    if (i < n * HH) g_z[i] = 0.0f;
    if (i < n * D)  g_acc[i] = 0.0f;
}

// ---------------- K7: residual + LN2 -> x2 fp32, h2 bf16 hi/lo ----------------
__global__ void k_resid_ln2(const float* __restrict__ x, const float* __restrict__ alpha,
                            const float* __restrict__ g2, const float* __restrict__ b2,
                            int n) {
    int row = blockIdx.x * 8 + (threadIdx.x >> 5);
    if (row >= n) return;
    int lane = threadIdx.x & 31;
    float a = alpha[0];
    float4 xv = ((const float4*)x)[(size_t)row * 32 + lane];
    float4 av = ((const float4*)g_acc)[(size_t)row * 32 + lane];
    float4 sv = *(const float4*)&g_qkvs[(size_t)row * 512 + 384 + lane * 4];
    float inv = 1.0f / (g_z[(size_t)row * HH + (lane >> 2)] + 1e-16f);
    float4 o;
    o.x = xv.x + a * (av.x * inv + sv.x);
    o.y = xv.y + a * (av.y * inv + sv.y);
    o.z = xv.z + a * (av.z * inv + sv.z);
    o.w = xv.w + a * (av.w * inv + sv.w);
    ((float4*)g_x2)[(size_t)row * 32 + lane] = o;
    float s  = o.x + o.y + o.z + o.w;
    float ss = fmaf(o.x, o.x, fmaf(o.y, o.y, fmaf(o.z, o.z, o.w * o.w)));
#pragma unroll
    for (int off = 16; off > 0; off >>= 1) {
        s  += __shfl_xor_sync(0xFFFFFFFFu, s, off);
        ss += __shfl_xor_sync(0xFFFFFFFFu, ss, off);
    }
    float mu  = s * (1.0f / 128.0f);
    float var = ss * (1.0f / 128.0f) - mu * mu;
    float r   = rsqrtf(var + 1e-5f);
    float4 gg = ((const float4*)g2)[lane];
    float4 bb = ((const float4*)b2)[lane];
    float o0 = (o.x - mu) * r * gg.x + bb.x;
    float o1 = (o.y - mu) * r * gg.y + bb.y;
    float o2 = (o.z - mu) * r * gg.z + bb.z;
    float o3 = (o.w - mu) * r * gg.w + bb.w;
    __nv_bfloat16 h0 = __float2bfloat16(o0), h1 = __float2bfloat16(o1);
    __nv_bfloat16 h2 = __float2bfloat16(o2), h3 = __float2bfloat16(o3);
    size_t base = (size_t)row * 128 + lane * 4;
    *(__nv_bfloat162*)&g_h2H[base]     = __nv_bfloat162(h0, h1);
    *(__nv_bfloat162*)&g_h2H[base + 2] = __nv_bfloat162(h2, h3);
    *(__nv_bfloat162*)&g_h2L[base]     =
        __nv_bfloat162(__float2bfloat16(o0 - __bfloat162float(h0)),
                       __float2bfloat16(o1 - __bfloat162float(h1)));
    *(__nv_bfloat162*)&g_h2L[base + 2] =
        __nv_bfloat162(__float2bfloat16(o2 - __bfloat162float(h2)),
                       __float2bfloat16(o3 - __bfloat162float(h3)));
}

// ---------------- launch ----------------
extern "C" void kernel_launch(void* const* d_in, const int* in_sizes, int n_in,
                              void* d_out, int out_size) {
    const float* x      = (const float*)d_in[0];
    const float* eattr  = (const float*)d_in[1];
    const int*   ei     = (const int*)d_in[2];
    const float* Wq     = (const float*)d_in[3];
    const float* bq     = (const float*)d_in[4];
    const float* Wk     = (const float*)d_in[5];
    const float* bk     = (const float*)d_in[6];
    const float* Wv     = (const float*)d_in[7];
    const float* bv     = (const float*)d_in[8];
    const float* We     = (const float*)d_in[9];
    const float* Wskip  = (const float*)d_in[10];
    const float* bskip  = (const float*)d_in[11];
    const float* W1     = (const float*)d_in[12];
    const float* b1     = (const float*)d_in[13];
    const float* W2     = (const float*)d_in[14];
    const float* b2     = (const float*)d_in[15];
    const float* g1     = (const float*)d_in[16];
    const float* beta1  = (const float*)d_in[17];
    const float* g2     = (const float*)d_in[18];
    const float* beta2  = (const float*)d_in[19];
    const float* alpha  = (const float*)d_in[20];

    int n = in_sizes[0] / D;   // 50000
    int E = in_sizes[1] / D;   // 600000
    float* out = (float*)d_out;

    int rowTiles = (n + 127) / 128;       // 391
    int edgeTiles = (E + 127) / 128;      // 4688

    static bool init_done = false;
    static __nv_bfloat16 *pH, *pL, *phH, *phL, *ph2H, *ph2L, *puH, *puL;
    static float *pqkvs, *px2, *pbias;
    if (!init_done) {
        cudaFuncSetAttribute(k_edge_mma, cudaFuncAttributeMaxDynamicSharedMemorySize,
                             EDGE_SMEM);
        cudaFuncSetAttribute(k_dense_bf, cudaFuncAttributeMaxDynamicSharedMemorySize,
                             DENSE_SMEM);
        cudaGetSymbolAddress((void**)&pH, g_BtH);
        cudaGetSymbolAddress((void**)&pL, g_BtL);
        cudaGetSymbolAddress((void**)&phH, g_hH);
        cudaGetSymbolAddress((void**)&phL, g_hL);
        cudaGetSymbolAddress((void**)&ph2H, g_h2H);
        cudaGetSymbolAddress((void**)&ph2L, g_h2L);
        cudaGetSymbolAddress((void**)&puH, g_uH);
        cudaGetSymbolAddress((void**)&puL, g_uL);
        cudaGetSymbolAddress((void**)&pqkvs, g_qkvs);
        cudaGetSymbolAddress((void**)&px2, g_x2);
        cudaGetSymbolAddress((void**)&pbias, g_bqkvs);
        init_done = true;
    }

    k_preconv<<<(BT_TOTAL + 255) / 256, 256>>>(Wq, Wk, Wv, Wskip, We, W1, W2);
    k_bias<<<2, 256>>>(bq, bk, bv, bskip);
    k_ln1<<<(n + 7) / 8, 256>>>(x, g1, beta1, n);
    k_init<<<(n * D + 255) / 256, 256>>>(n);

    // fused node projections -> g_qkvs [N][512]
    {
        dim3 grid(rowTiles, 4);
        k_dense_bf<<<grid, 256, DENSE_SMEM>>>(phH, phL, 128, pH + OFF_WQ, pL + OFF_WQ, 128,
                                              pbias, pqkvs, nullptr, nullptr, 512,
                                              nullptr, 0, n);
    }
    k_edge_mma<<<edgeTiles, 256, EDGE_SMEM>>>(eattr, ei, E, n);
    k_resid_ln2<<<(n + 7) / 8, 256>>>(x, alpha, g2, beta2, n);
    {
        dim3 grid(rowTiles, 4);
        k_dense_bf<<<grid, 256, DENSE_SMEM>>>(ph2H, ph2L, 128, pH + OFF_W1, pL + OFF_W1, 128,
                                              b1, nullptr, puH, puL, 512, nullptr, 1, n);
    }
    k_dense_bf<<<rowTiles, 256, DENSE_SMEM>>>(puH, puL, 512, pH + OFF_W2, pL + OFF_W2, 512,
                                              b2, out, nullptr, nullptr, 128, px2, 2, n);
}